// round 6
// baseline (speedup 1.0000x reference)
#include <cuda_runtime.h>
#include <cstdint>

// LSTMModelClassify: B=2048, T=512, D=1, H=50, C=2, 2-layer LSTM + FC.
// R6: TPB=576, role-partitioned. Phase A (concurrent): warps 0-7 do Whh0@h1
// with register weights; warps 8-15 do Whh1@h2 with register weights.
// Phase B: 512 threads stream Wih1 k-halves from smem @ new h1.
// Partial-sum planes in smem combined by elementwise phases.

#define TPB 576
constexpr int NB    = 14;
constexpr int Hh    = 50;
constexpr int G4    = 200;
constexpr int Tt    = 512;
constexpr int BATCH = 2048;
constexpr int NC    = 2;
constexpr int HS    = 52;    // h-state row stride (50 + 2 zero pad)
constexpr int PS    = 17;    // partial-plane stride (odd -> conflict-free)

// shared memory layout (floats)
constexpr int OFF_W1   = 0;                     // Wih1 [200][52]
constexpr int OFF_XS   = OFF_W1   + G4 * HS;    // x slice [14][512]
constexpr int OFF_BUFA = OFF_XS   + NB * Tt;    // h1 [14][52]
constexpr int OFF_BUFB = OFF_BUFA + NB * HS;    // h2 [14][52]
constexpr int OFF_P0   = OFF_BUFB + NB * HS;    // plane0: l1 preact / l2 p1a
constexpr int OFF_P1   = OFF_P0   + G4 * PS;    // plane1: Whh1 partial (+bias1)
constexpr int OFF_P2   = OFF_P1   + G4 * PS;    // plane2: l2 p1b
constexpr int OFF_WFC  = OFF_P2   + G4 * PS;
constexpr int OFF_BFC  = OFF_WFC  + NC * Hh;
constexpr int SMEMF    = OFF_BFC  + NC;         // ~29.3K floats ≈ 117KB

__device__ __forceinline__ unsigned long long ffma2(unsigned long long a,
                                                    unsigned long long b,
                                                    unsigned long long c) {
    unsigned long long d;
    asm("fma.rn.f32x2 %0, %1, %2, %3;" : "=l"(d) : "l"(a), "l"(b), "l"(c));
    return d;
}

__device__ __forceinline__ void unpack2(unsigned long long a, float& x, float& y) {
    unsigned lo, hi;
    asm("mov.b64 {%0, %1}, %2;" : "=r"(lo), "=r"(hi) : "l"(a));
    x = __uint_as_float(lo);
    y = __uint_as_float(hi);
}

__device__ __forceinline__ float sigf(float x) {
    float e = __expf(-x);
    return __fdividef(1.0f, 1.0f + e);
}
__device__ __forceinline__ float tanh_(float x) {
    float e = __expf(2.0f * x);
    return 1.0f - __fdividef(2.0f, 1.0f + e);
}

// Phase-B MAC: stream NK4 k-quads of Wih1 from smem, h broadcast, 7 batches.
template <int NK4>
__device__ __forceinline__ void macB(const float* __restrict__ wrow,
                                     const float* __restrict__ hbuf,
                                     unsigned long long (&acc)[7]) {
#pragma unroll
    for (int k4 = 0; k4 < NK4; ++k4) {
        ulonglong2 wv = *reinterpret_cast<const ulonglong2*>(wrow + 4 * k4);
#pragma unroll
        for (int b = 0; b < 7; ++b) {
            ulonglong2 hv = *reinterpret_cast<const ulonglong2*>(hbuf + b * HS + 4 * k4);
            acc[b] = ffma2(hv.x, wv.x, acc[b]);
            acc[b] = ffma2(hv.y, wv.y, acc[b]);
        }
    }
}

__global__ void __launch_bounds__(TPB, 1) lstm_kernel(
    const float* __restrict__ x,
    const float* __restrict__ Wih0, const float* __restrict__ Whh0,
    const float* __restrict__ bih0, const float* __restrict__ bhh0,
    const float* __restrict__ Wih1, const float* __restrict__ Whh1,
    const float* __restrict__ bih1, const float* __restrict__ bhh1,
    const float* __restrict__ Wfc,  const float* __restrict__ bfc,
    float* __restrict__ out)
{
    extern __shared__ __align__(16) float sm[];
    const int tid = threadIdx.x;
    const int b0  = blockIdx.x * NB;

    for (int i = tid; i < SMEMF; i += TPB) sm[i] = 0.0f;   // zero: pads + h init
    __syncthreads();

    float* W1   = sm + OFF_W1;
    float* xs   = sm + OFF_XS;
    float* bufA = sm + OFF_BUFA;
    float* bufB = sm + OFF_BUFB;
    float* P0   = sm + OFF_P0;
    float* P1   = sm + OFF_P1;
    float* P2   = sm + OFF_P2;
    float* wfc  = sm + OFF_WFC;
    float* bfcs = sm + OFF_BFC;

    // stage Wih1 to smem; x slice; fc
    for (int i = tid; i < G4 * Hh; i += TPB) {
        int g = i / Hh, k = i % Hh;
        W1[g * HS + k] = Wih1[i];
    }
    for (int i = tid; i < NB * Tt; i += TPB) {
        int b = i / Tt, t = i % Tt;
        int gb = b0 + b;
        xs[i] = (gb < BATCH) ? x[gb * Tt + t] : 0.0f;
    }
    for (int i = tid; i < NC * Hh; i += TPB) wfc[i] = Wfc[i];
    if (tid < NC) bfcs[tid] = bfc[tid];

    // ---- roles ----
    const bool isMac = tid < 512;
    const int  role  = tid >> 8;                 // 0: Whh0 / Wih1-half0; 1: Whh1 / Wih1-half1
    const int  gslot = tid & 255;
    const int  gidx  = gslot < G4 ? gslot : G4 - 1;     // clamp dummies
    const bool gstore = isMac && (gslot < G4);

    // phase-A register weights (26 u64 = 52 floats incl pad)
    unsigned long long w[26];
    float bias_a = 0.f, wxg = 0.f;
    if (isMac) {
        const float* wsrc = (role == 0) ? (Whh0 + gidx * Hh) : (Whh1 + gidx * Hh);
        const unsigned long long* ws = reinterpret_cast<const unsigned long long*>(wsrc);
#pragma unroll
        for (int i = 0; i < 25; ++i) w[i] = ws[i];
        w[25] = 0ULL;
        if (role == 0) { bias_a = bih0[gidx] + bhh0[gidx]; wxg = Wih0[gidx]; }
        else           { bias_a = bih1[gidx] + bhh1[gidx]; }
    }
    const float* hbufA  = (role == 0) ? bufA : bufB;   // phase-A h source
    float*       planeA = (role == 0) ? P0   : P1;     // phase-A partial dest
    float*       planeB = (role == 0) ? P0   : P2;     // phase-B partial dest
    const float* wrowB  = W1 + gidx * HS + role * 28;  // phase-B weight row (k-half)

    // elementwise state: cells u, u+576
    float c1s[2] = {0.f, 0.f}, c2s[2] = {0.f, 0.f};

    __syncthreads();

    for (int t = 0; t < Tt; ++t) {
        // ---- Phase A: Whh0@h1(t-1)  ||  Whh1@h2(t-1)  (register weights) ----
        if (isMac) {
#pragma unroll
            for (int pass = 0; pass < 2; ++pass) {
                const int bb = 7 * pass;
                const float* hb = hbufA + bb * HS;
                unsigned long long acc[7];
#pragma unroll
                for (int b = 0; b < 7; ++b) acc[b] = 0ULL;
#pragma unroll
                for (int k4 = 0; k4 < 13; ++k4) {
#pragma unroll
                    for (int b = 0; b < 7; ++b) {
                        ulonglong2 hv = *reinterpret_cast<const ulonglong2*>(hb + b * HS + 4 * k4);
                        acc[b] = ffma2(hv.x, w[2 * k4],     acc[b]);
                        acc[b] = ffma2(hv.y, w[2 * k4 + 1], acc[b]);
                    }
                }
                if (gstore) {
#pragma unroll
                    for (int b = 0; b < 7; ++b) {
                        float lo, hi;
                        unpack2(acc[b], lo, hi);
                        float extra = (role == 0)
                            ? fmaf(wxg, xs[(bb + b) * Tt + t], bias_a)
                            : bias_a;
                        planeA[gidx * PS + bb + b] = lo + hi + extra;
                    }
                }
            }
        }
        __syncthreads();

        // ---- Layer 1 elementwise: P0 (full preact) -> bufA = h1(t) ----
#pragma unroll
        for (int r = 0; r < 2; ++r) {
            int u = tid + TPB * r;
            if (u < Hh * NB) {
                int b = u / Hh, j = u % Hh;
                float gi = P0[j * PS + b];
                float gf = P0[(j + 50) * PS + b];
                float gg = P0[(j + 100) * PS + b];
                float go = P0[(j + 150) * PS + b];
                float cc = sigf(gf) * c1s[r] + sigf(gi) * tanh_(gg);
                c1s[r] = cc;
                bufA[b * HS + j] = sigf(go) * tanh_(cc);
            }
        }
        __syncthreads();

        // ---- Phase B: Wih1 @ h1(t), k-halves streamed from smem ----
        if (isMac) {
#pragma unroll
            for (int pass = 0; pass < 2; ++pass) {
                const int bb = 7 * pass;
                const float* hb = bufA + bb * HS + role * 28;
                unsigned long long acc[7];
#pragma unroll
                for (int b = 0; b < 7; ++b) acc[b] = 0ULL;
                if (role == 0) macB<7>(wrowB, hb, acc);
                else           macB<6>(wrowB, hb, acc);
                if (gstore) {
#pragma unroll
                    for (int b = 0; b < 7; ++b) {
                        float lo, hi;
                        unpack2(acc[b], lo, hi);
                        planeB[gidx * PS + bb + b] = lo + hi;
                    }
                }
            }
        }
        __syncthreads();

        // ---- Layer 2 elementwise: P0 + P1(+bias1) + P2 -> bufB = h2(t) ----
#pragma unroll
        for (int r = 0; r < 2; ++r) {
            int u = tid + TPB * r;
            if (u < Hh * NB) {
                int b = u / Hh, j = u % Hh;
                float gi = P0[j * PS + b]        + P1[j * PS + b]        + P2[j * PS + b];
                float gf = P0[(j + 50) * PS + b] + P1[(j + 50) * PS + b] + P2[(j + 50) * PS + b];
                float gg = P0[(j + 100) * PS + b]+ P1[(j + 100) * PS + b]+ P2[(j + 100) * PS + b];
                float go = P0[(j + 150) * PS + b]+ P1[(j + 150) * PS + b]+ P2[(j + 150) * PS + b];
                float cc = sigf(gf) * c2s[r] + sigf(gi) * tanh_(gg);
                c2s[r] = cc;
                bufB[b * HS + j] = sigf(go) * tanh_(cc);
            }
        }
        __syncthreads();
    }

    // ---- Final FC on last h2 ----
    if (tid < NB * NC) {
        int bl = tid >> 1;
        int c  = tid & 1;
        int gb = b0 + bl;
        if (gb < BATCH) {
            float s = bfcs[c];
#pragma unroll
            for (int j = 0; j < Hh; ++j) s += wfc[c * Hh + j] * bufB[bl * HS + j];
            out[gb * NC + c] = s;
        }
    }
}

extern "C" void kernel_launch(void* const* d_in, const int* in_sizes, int n_in,
                              void* d_out, int out_size) {
    const float* x    = (const float*)d_in[0];
    const float* Wih0 = (const float*)d_in[1];
    const float* Whh0 = (const float*)d_in[2];
    const float* bih0 = (const float*)d_in[3];
    const float* bhh0 = (const float*)d_in[4];
    const float* Wih1 = (const float*)d_in[5];
    const float* Whh1 = (const float*)d_in[6];
    const float* bih1 = (const float*)d_in[7];
    const float* bhh1 = (const float*)d_in[8];
    const float* Wfc  = (const float*)d_in[9];
    const float* bfc  = (const float*)d_in[10];
    float* out = (float*)d_out;

    const int smem_bytes = SMEMF * (int)sizeof(float);
    cudaFuncSetAttribute(lstm_kernel, cudaFuncAttributeMaxDynamicSharedMemorySize, smem_bytes);

    const int grid = (BATCH + NB - 1) / NB;   // 147 blocks, one wave
    lstm_kernel<<<grid, TPB, smem_bytes>>>(x, Wih0, Whh0, bih0, bhh0,
                                           Wih1, Whh1, bih1, bhh1,
                                           Wfc, bfc, out);
}

// round 7
// speedup vs baseline: 1.1935x; 1.1935x over previous
#include <cuda_runtime.h>
#include <cstdint>

// LSTMModelClassify: B=2048, T=512, D=1, H=50, C=2, 2-layer LSTM + FC.
// R7: k-split register weights. Thread t<400: g=t>>1, kh=t&1.
// Each thread holds its (gate, k-half) slices of Whh0/Wih1/Whh1 in 42 u64 regs.
// No weight smem streaming. Partial planes P0 (kh0, +bias+x) and P1 (kh1).
// TPB=480 (15 warps) -> reg cap 136.

#define TPB 480
constexpr int NB    = 14;
constexpr int Hh    = 50;
constexpr int G4    = 200;
constexpr int Tt    = 512;
constexpr int BATCH = 2048;
constexpr int NC    = 2;
constexpr int HS    = 52;    // h-state row stride (50 + 2 zero pad)
constexpr int PS    = 17;    // plane row stride
constexpr int PSZ   = G4 * PS;        // 3400

// shared memory layout (floats)
constexpr int OFF_XS   = 0;                     // x slice [14][512]
constexpr int OFF_BUFA = OFF_XS   + NB * Tt;    // h1 [14][52]
constexpr int OFF_BUFB = OFF_BUFA + NB * HS;    // h2 [14][52]
constexpr int OFF_P0   = OFF_BUFB + NB * HS;    // kh0 partial (incl bias + x)
constexpr int OFF_P1   = OFF_P0   + PSZ + 25;   // gap 3425 ≡ 1 (mod 32): no STS conflicts
constexpr int OFF_WFC  = OFF_P1   + PSZ;
constexpr int OFF_BFC  = OFF_WFC  + NC * Hh;
constexpr int SMEMF    = OFF_BFC  + NC;         // ~15.6K floats ≈ 62KB

__device__ __forceinline__ unsigned long long ffma2(unsigned long long a,
                                                    unsigned long long b,
                                                    unsigned long long c) {
    unsigned long long d;
    asm("fma.rn.f32x2 %0, %1, %2, %3;" : "=l"(d) : "l"(a), "l"(b), "l"(c));
    return d;
}

__device__ __forceinline__ void unpack2(unsigned long long a, float& x, float& y) {
    unsigned lo, hi;
    asm("mov.b64 {%0, %1}, %2;" : "=r"(lo), "=r"(hi) : "l"(a));
    x = __uint_as_float(lo);
    y = __uint_as_float(hi);
}

__device__ __forceinline__ float sigf(float x) {
    float e = __expf(-x);
    return __fdividef(1.0f, 1.0f + e);
}
__device__ __forceinline__ float tanh_(float x) {
    float e = __expf(2.0f * x);
    return 1.0f - __fdividef(2.0f, 1.0f + e);
}

__global__ void __launch_bounds__(TPB, 1) lstm_kernel(
    const float* __restrict__ x,
    const float* __restrict__ Wih0, const float* __restrict__ Whh0,
    const float* __restrict__ bih0, const float* __restrict__ bhh0,
    const float* __restrict__ Wih1, const float* __restrict__ Whh1,
    const float* __restrict__ bih1, const float* __restrict__ bhh1,
    const float* __restrict__ Wfc,  const float* __restrict__ bfc,
    float* __restrict__ out)
{
    extern __shared__ __align__(16) float sm[];
    const int tid = threadIdx.x;
    const int b0  = blockIdx.x * NB;

    for (int i = tid; i < SMEMF; i += TPB) sm[i] = 0.0f;   // zero: pads + h init
    __syncthreads();

    float* xs   = sm + OFF_XS;
    float* bufA = sm + OFF_BUFA;
    float* bufB = sm + OFF_BUFB;
    float* P0   = sm + OFF_P0;
    float* P1   = sm + OFF_P1;
    float* wfc  = sm + OFF_WFC;
    float* bfcs = sm + OFF_BFC;

    // stage x slice, fc weights
    for (int i = tid; i < NB * Tt; i += TPB) {
        int b = i / Tt, t = i % Tt;
        int gb = b0 + b;
        xs[i] = (gb < BATCH) ? x[gb * Tt + t] : 0.0f;
    }
    for (int i = tid; i < NC * Hh; i += TPB) wfc[i] = Wfc[i];
    if (tid < NC) bfcs[tid] = bfc[tid];

    // ---- mac role: t<400: g = t>>1, kh = t&1 ----
    const bool mac = tid < 400;
    const int  g   = mac ? (tid >> 1) : 0;
    const int  kh  = tid & 1;
    const int  khbase = kh * 12;           // u64-pair base: 0 or 12
    const int  khoff  = kh * 24;           // float offset into 52-float h rows

    // register weights: pairs khbase..khbase+13.
    // kh0: pairs 0..13 all real (floats 0..27).
    // kh1: pairs 12..25; real only i in [2,12] (pairs 14..24 = floats 28..49).
    unsigned long long wA[14], wB[14], wC[14];
#pragma unroll
    for (int i = 0; i < 14; ++i) {
        int p = khbase + i;
        bool real = mac && ((kh == 0) || (i >= 2 && i <= 12));
        wA[i] = real ? *reinterpret_cast<const unsigned long long*>(Whh0 + g * Hh + 2 * p) : 0ULL;
        wB[i] = real ? *reinterpret_cast<const unsigned long long*>(Wih1 + g * Hh + 2 * p) : 0ULL;
        wC[i] = real ? *reinterpret_cast<const unsigned long long*>(Whh1 + g * Hh + 2 * p) : 0ULL;
    }
    float bias0 = 0.f, bias1 = 0.f, wxg = 0.f;
    if (mac && kh == 0) {
        bias0 = bih0[g] + bhh0[g];
        bias1 = bih1[g] + bhh1[g];
        wxg   = Wih0[g];
    }
    float* pl = (kh == 0) ? P0 : P1;

    // elementwise role: 700 cells over 480 threads (<=2 each)
    float c1s[2] = {0.f, 0.f}, c2s[2] = {0.f, 0.f};

    __syncthreads();

    for (int t = 0; t < Tt; ++t) {
        // ---- MAC L1: partial(g,kh) = sum_k Whh0[g][k] * h1[b][k] over this k-half ----
        if (mac) {
#pragma unroll
            for (int pass = 0; pass < 2; ++pass) {
                const int bb = 7 * pass;
                const float* hb = bufA + bb * HS + khoff;
                unsigned long long acc[7];
#pragma unroll
                for (int b = 0; b < 7; ++b) acc[b] = 0ULL;
#pragma unroll
                for (int k4 = 0; k4 < 7; ++k4) {
#pragma unroll
                    for (int b = 0; b < 7; ++b) {
                        ulonglong2 hv = *reinterpret_cast<const ulonglong2*>(hb + b * HS + 4 * k4);
                        acc[b] = ffma2(hv.x, wA[2 * k4],     acc[b]);
                        acc[b] = ffma2(hv.y, wA[2 * k4 + 1], acc[b]);
                    }
                }
#pragma unroll
                for (int b = 0; b < 7; ++b) {
                    float lo, hi;
                    unpack2(acc[b], lo, hi);
                    float extra = (kh == 0) ? fmaf(wxg, xs[(bb + b) * Tt + t], bias0) : 0.0f;
                    pl[g * PS + bb + b] = lo + hi + extra;
                }
            }
        }
        __syncthreads();

        // ---- L1 elementwise: P0 + P1 -> bufA = h1(t) ----
#pragma unroll
        for (int r = 0; r < 2; ++r) {
            int u = tid + TPB * r;
            if (u < Hh * NB) {
                int b = u / Hh, j = u % Hh;
                float gi = P0[j * PS + b]         + P1[j * PS + b];
                float gf = P0[(j + 50) * PS + b]  + P1[(j + 50) * PS + b];
                float gg = P0[(j + 100) * PS + b] + P1[(j + 100) * PS + b];
                float go = P0[(j + 150) * PS + b] + P1[(j + 150) * PS + b];
                float cc = sigf(gf) * c1s[r] + sigf(gi) * tanh_(gg);
                c1s[r] = cc;
                bufA[b * HS + j] = sigf(go) * tanh_(cc);
            }
        }
        __syncthreads();

        // ---- MAC L2: Wih1 @ h1(t) + Whh1 @ h2(t-1), this k-half ----
        if (mac) {
#pragma unroll
            for (int pass = 0; pass < 2; ++pass) {
                const int bb = 7 * pass;
                const float* hbA = bufA + bb * HS + khoff;
                const float* hbB = bufB + bb * HS + khoff;
                unsigned long long acc[7];
#pragma unroll
                for (int b = 0; b < 7; ++b) acc[b] = 0ULL;
#pragma unroll
                for (int k4 = 0; k4 < 7; ++k4) {
#pragma unroll
                    for (int b = 0; b < 7; ++b) {
                        ulonglong2 hvA = *reinterpret_cast<const ulonglong2*>(hbA + b * HS + 4 * k4);
                        acc[b] = ffma2(hvA.x, wB[2 * k4],     acc[b]);
                        acc[b] = ffma2(hvA.y, wB[2 * k4 + 1], acc[b]);
                        ulonglong2 hvB = *reinterpret_cast<const ulonglong2*>(hbB + b * HS + 4 * k4);
                        acc[b] = ffma2(hvB.x, wC[2 * k4],     acc[b]);
                        acc[b] = ffma2(hvB.y, wC[2 * k4 + 1], acc[b]);
                    }
                }
#pragma unroll
                for (int b = 0; b < 7; ++b) {
                    float lo, hi;
                    unpack2(acc[b], lo, hi);
                    float extra = (kh == 0) ? bias1 : 0.0f;
                    pl[g * PS + bb + b] = lo + hi + extra;
                }
            }
        }
        __syncthreads();

        // ---- L2 elementwise: P0 + P1 -> bufB = h2(t) ----
#pragma unroll
        for (int r = 0; r < 2; ++r) {
            int u = tid + TPB * r;
            if (u < Hh * NB) {
                int b = u / Hh, j = u % Hh;
                float gi = P0[j * PS + b]         + P1[j * PS + b];
                float gf = P0[(j + 50) * PS + b]  + P1[(j + 50) * PS + b];
                float gg = P0[(j + 100) * PS + b] + P1[(j + 100) * PS + b];
                float go = P0[(j + 150) * PS + b] + P1[(j + 150) * PS + b];
                float cc = sigf(gf) * c2s[r] + sigf(gi) * tanh_(gg);
                c2s[r] = cc;
                bufB[b * HS + j] = sigf(go) * tanh_(cc);
            }
        }
        __syncthreads();
    }

    // ---- Final FC on last h2 ----
    if (tid < NB * NC) {
        int bl = tid >> 1;
        int c  = tid & 1;
        int gb = b0 + bl;
        if (gb < BATCH) {
            float s = bfcs[c];
#pragma unroll
            for (int j = 0; j < Hh; ++j) s += wfc[c * Hh + j] * bufB[bl * HS + j];
            out[gb * NC + c] = s;
        }
    }
}

extern "C" void kernel_launch(void* const* d_in, const int* in_sizes, int n_in,
                              void* d_out, int out_size) {
    const float* x    = (const float*)d_in[0];
    const float* Wih0 = (const float*)d_in[1];
    const float* Whh0 = (const float*)d_in[2];
    const float* bih0 = (const float*)d_in[3];
    const float* bhh0 = (const float*)d_in[4];
    const float* Wih1 = (const float*)d_in[5];
    const float* Whh1 = (const float*)d_in[6];
    const float* bih1 = (const float*)d_in[7];
    const float* bhh1 = (const float*)d_in[8];
    const float* Wfc  = (const float*)d_in[9];
    const float* bfc  = (const float*)d_in[10];
    float* out = (float*)d_out;

    const int smem_bytes = SMEMF * (int)sizeof(float);
    cudaFuncSetAttribute(lstm_kernel, cudaFuncAttributeMaxDynamicSharedMemorySize, smem_bytes);

    const int grid = (BATCH + NB - 1) / NB;   // 147 blocks, one wave
    lstm_kernel<<<grid, TPB, smem_bytes>>>(x, Wih0, Whh0, bih0, bhh0,
                                           Wih1, Whh1, bih1, bhh1,
                                           Wfc, bfc, out);
}